// round 5
// baseline (speedup 1.0000x reference)
#include <cuda_runtime.h>
#include <math.h>

#define DIM   1024
#define BT    2
#define NT    2048
#define HEADS 16
#define HD    64
#define MLPD  4096
#define ROWS  (BT*NT)          // 4096 token rows total

// ---------------------------------------------------------------------------
// Scratch (static device globals; runtime allocation is forbidden)
// ---------------------------------------------------------------------------
__device__ float g_mod [BT*6*DIM];     // adaLN modulation (B, 6C)
__device__ float g_xn  [ROWS*DIM];     // LN output (reused for LN1 and LN2)
__device__ float g_q   [ROWS*DIM];
__device__ float g_k   [ROWS*DIM];
__device__ float g_v   [ROWS*DIM];
__device__ float g_attn[ROWS*DIM];     // attention output before Wo
__device__ float g_h   [(size_t)ROWS*MLPD]; // MLP hidden (post-GELU)

// ---------------------------------------------------------------------------
// 1) mod = silu(t_emb) @ ada_W + ada_b        (B,1024)@(1024,6144)
// ---------------------------------------------------------------------------
__global__ void __launch_bounds__(256) silu_mod_kernel(
    const float* __restrict__ t_emb, const float* __restrict__ adaW,
    const float* __restrict__ adab, float* __restrict__ mod)
{
    __shared__ float st[DIM];
    int b = blockIdx.y;
    int j = blockIdx.x * 256 + threadIdx.x;      // 0..6143
    for (int i = threadIdx.x; i < DIM; i += 256) {
        float t = t_emb[b*DIM + i];
        st[i] = t / (1.f + __expf(-t));
    }
    __syncthreads();
    float acc = 0.f;
    #pragma unroll 4
    for (int kk = 0; kk < DIM; kk++)
        acc += st[kk] * adaW[(size_t)kk*6*DIM + j];
    mod[b*6*DIM + j] = acc + adab[j];
}

// ---------------------------------------------------------------------------
// 2) xn = LN(x)*g+b, then * (1+scale_mod) + shift_mod   (one block per row)
// ---------------------------------------------------------------------------
__global__ void __launch_bounds__(256) ln_mod_kernel(
    const float* __restrict__ x, float* __restrict__ out,
    const float* __restrict__ g, const float* __restrict__ bb,
    const float* __restrict__ mod, int shift_chunk, int scale_chunk)
{
    int row = blockIdx.x;
    int b   = row >> 11;                 // row / 2048
    int tid = threadIdx.x;
    const float* xr = x + (size_t)row*DIM;
    float4 xv = *(const float4*)(xr + tid*4);
    float s  = xv.x + xv.y + xv.z + xv.w;
    float s2 = xv.x*xv.x + xv.y*xv.y + xv.z*xv.z + xv.w*xv.w;
    #pragma unroll
    for (int o = 16; o > 0; o >>= 1) {
        s  += __shfl_xor_sync(0xffffffffu, s,  o);
        s2 += __shfl_xor_sync(0xffffffffu, s2, o);
    }
    __shared__ float ws[8], ws2[8];
    __shared__ float smu, srstd;
    int wid = tid >> 5;
    if ((tid & 31) == 0) { ws[wid] = s; ws2[wid] = s2; }
    __syncthreads();
    if (tid == 0) {
        float S = 0.f, S2 = 0.f;
        #pragma unroll
        for (int i = 0; i < 8; i++) { S += ws[i]; S2 += ws2[i]; }
        float mu  = S  * (1.f/DIM);
        float var = S2 * (1.f/DIM) - mu*mu;
        smu = mu; srstd = rsqrtf(var + 1e-5f);
    }
    __syncthreads();
    float mu = smu, rstd = srstd;
    int c = tid*4;
    const float* mb = mod + b*6*DIM;
    float4 gv = *(const float4*)(g  + c);
    float4 bv = *(const float4*)(bb + c);
    float4 sc = *(const float4*)(mb + scale_chunk*DIM + c);
    float4 sh = *(const float4*)(mb + shift_chunk*DIM + c);
    float4 y;
    y.x = ((xv.x-mu)*rstd*gv.x + bv.x)*(1.f+sc.x) + sh.x;
    y.y = ((xv.y-mu)*rstd*gv.y + bv.y)*(1.f+sc.y) + sh.y;
    y.z = ((xv.z-mu)*rstd*gv.z + bv.z)*(1.f+sc.z) + sh.z;
    y.w = ((xv.w-mu)*rstd*gv.w + bv.w)*(1.f+sc.w) + sh.w;
    *(float4*)(out + (size_t)row*DIM + c) = y;
}

// ---------------------------------------------------------------------------
// 3) Tiled SGEMM: Out(M,Nc) = A(M,K) @ W(K,Nc), row-major everywhere.
//    EPI 0: store;  EPI 1: exact GELU;  EPI 2: Out = res + gate[b][col]*acc
//    BM=BN=128, BK=16, 256 threads, 8x8 per thread (split 2x2 of 4x4).
// ---------------------------------------------------------------------------
template<int EPI>
__global__ void __launch_bounds__(256) gemm_kernel(
    const float* __restrict__ A, const float* __restrict__ W,
    float* __restrict__ Out, int M, int Nc, int K,
    const float* __restrict__ gate, const float* __restrict__ res)
{
    __shared__ float As[16][132];    // A tile transposed [k][m], +4 pad
    __shared__ float Bs[16][128];    // W tile [k][n]

    int tid = threadIdx.x;
    int m0 = blockIdx.y * 128;
    int n0 = blockIdx.x * 128;
    int tr4 = (tid >> 4) * 4;        // 0..60
    int tc4 = (tid & 15) * 4;        // 0..60

    int arow = tid >> 2;             // 0..63  (A tile row; +64 second half)
    int ac4  = (tid & 3) * 4;        // 0,4,8,12 (k within tile)
    int brow = tid >> 5;             // 0..7   (W tile k-row; +8 second half)
    int bc4  = (tid & 31) * 4;       // 0..124

    float acc[8][8];
    #pragma unroll
    for (int i = 0; i < 8; i++)
        #pragma unroll
        for (int j = 0; j < 8; j++) acc[i][j] = 0.f;

    for (int k0 = 0; k0 < K; k0 += 16) {
        float4 a0 = *(const float4*)(A + (size_t)(m0+arow)   *K + k0 + ac4);
        float4 a1 = *(const float4*)(A + (size_t)(m0+arow+64)*K + k0 + ac4);
        float4 b0 = *(const float4*)(W + (size_t)(k0+brow)  *Nc + n0 + bc4);
        float4 b1 = *(const float4*)(W + (size_t)(k0+brow+8)*Nc + n0 + bc4);
        __syncthreads();
        As[ac4+0][arow] = a0.x; As[ac4+1][arow] = a0.y;
        As[ac4+2][arow] = a0.z; As[ac4+3][arow] = a0.w;
        As[ac4+0][arow+64] = a1.x; As[ac4+1][arow+64] = a1.y;
        As[ac4+2][arow+64] = a1.z; As[ac4+3][arow+64] = a1.w;
        *(float4*)&Bs[brow  ][bc4] = b0;
        *(float4*)&Bs[brow+8][bc4] = b1;
        __syncthreads();
        #pragma unroll
        for (int kk = 0; kk < 16; kk++) {
            float a[8], bf[8];
            *(float4*)(a)    = *(const float4*)&As[kk][tr4];
            *(float4*)(a+4)  = *(const float4*)&As[kk][tr4+64];
            *(float4*)(bf)   = *(const float4*)&Bs[kk][tc4];
            *(float4*)(bf+4) = *(const float4*)&Bs[kk][tc4+64];
            #pragma unroll
            for (int ii = 0; ii < 8; ii++)
                #pragma unroll
                for (int jj = 0; jj < 8; jj++)
                    acc[ii][jj] += a[ii]*bf[jj];
        }
    }

    #pragma unroll
    for (int ih = 0; ih < 2; ih++) {
        #pragma unroll
        for (int ii = 0; ii < 4; ii++) {
            int row = m0 + tr4 + ih*64 + ii;
            #pragma unroll
            for (int jh = 0; jh < 2; jh++) {
                int col = n0 + tc4 + jh*64;
                float4 vv;
                vv.x = acc[ih*4+ii][jh*4+0];
                vv.y = acc[ih*4+ii][jh*4+1];
                vv.z = acc[ih*4+ii][jh*4+2];
                vv.w = acc[ih*4+ii][jh*4+3];
                if (EPI == 1) {
                    vv.x = 0.5f*vv.x*(1.f + erff(vv.x*0.70710678f));
                    vv.y = 0.5f*vv.y*(1.f + erff(vv.y*0.70710678f));
                    vv.z = 0.5f*vv.z*(1.f + erff(vv.z*0.70710678f));
                    vv.w = 0.5f*vv.w*(1.f + erff(vv.w*0.70710678f));
                } else if (EPI == 2) {
                    int bb = row >> 11;
                    float4 g4 = *(const float4*)(gate + bb*6*DIM + col);
                    float4 r4 = *(const float4*)(res + (size_t)row*Nc + col);
                    vv.x = r4.x + g4.x*vv.x;
                    vv.y = r4.y + g4.y*vv.y;
                    vv.z = r4.z + g4.z*vv.z;
                    vv.w = r4.w + g4.w*vv.w;
                }
                *(float4*)(Out + (size_t)row*Nc + col) = vv;
            }
        }
    }
}

// ---------------------------------------------------------------------------
// 4) RoPE (in-place on q and k). One thread per (b, n, h): 64 contiguous floats.
//    rotate_half: rot[j] = -x[2j+1], rot[32+j] = x[2j]  (j<32)
//    cos/sin index: angle[i] = n * invf[i mod 32]
// ---------------------------------------------------------------------------
__global__ void __launch_bounds__(256) rope_kernel(float* __restrict__ q,
                                                   float* __restrict__ k)
{
    int idx = blockIdx.x*256 + threadIdx.x;          // 0..65535
    int n = (idx >> 4) & (NT-1);                      // token index
    float cs[32], sn[32];
    #pragma unroll
    for (int j = 0; j < 32; j++) {
        float invf = expf((float)j * -0.2878231366f); // -ln(10000)/32
        float ang  = (float)n * invf;
        sincosf(ang, &sn[j], &cs[j]);
    }
    float* ptrs[2]; ptrs[0] = q + (size_t)idx*64; ptrs[1] = k + (size_t)idx*64;
    #pragma unroll
    for (int tpi = 0; tpi < 2; tpi++) {
        float* p = ptrs[tpi];
        float buf[64];
        #pragma unroll
        for (int u = 0; u < 16; u++) {
            float4 t = *(const float4*)(p + u*4);
            buf[u*4+0] = t.x; buf[u*4+1] = t.y; buf[u*4+2] = t.z; buf[u*4+3] = t.w;
        }
        #pragma unroll
        for (int t = 0; t < 8; t++) {
            float4 lo, hi;
            lo.x = buf[4*t+0]*cs[4*t+0] - buf[8*t+1]*sn[4*t+0];
            lo.y = buf[4*t+1]*cs[4*t+1] - buf[8*t+3]*sn[4*t+1];
            lo.z = buf[4*t+2]*cs[4*t+2] - buf[8*t+5]*sn[4*t+2];
            lo.w = buf[4*t+3]*cs[4*t+3] - buf[8*t+7]*sn[4*t+3];
            hi.x = buf[32+4*t+0]*cs[4*t+0] + buf[8*t+0]*sn[4*t+0];
            hi.y = buf[32+4*t+1]*cs[4*t+1] + buf[8*t+2]*sn[4*t+1];
            hi.z = buf[32+4*t+2]*cs[4*t+2] + buf[8*t+4]*sn[4*t+2];
            hi.w = buf[32+4*t+3]*cs[4*t+3] + buf[8*t+6]*sn[4*t+3];
            *(float4*)(p + 4*t)      = lo;
            *(float4*)(p + 32 + 4*t) = hi;
        }
    }
}

// ---------------------------------------------------------------------------
// 5) Flash attention, fp32. Block = (q-tile of 64 rows) x (b,h). 256 threads.
//    Thread owns row r=tid/4 and 16-wide col/dim slice cs=(tid&3)*16.
//    smem: Qs[64][68], Kt[64][68] (d-major), Ss[64][68], Vs[64][64]  = 67 KB
// ---------------------------------------------------------------------------
#define FL_SMEM_FLOATS (3*64*68 + 64*64)
#define FL_SMEM_BYTES  (FL_SMEM_FLOATS*4)

__global__ void __launch_bounds__(256) flash_kernel(
    const float* __restrict__ q, const float* __restrict__ k,
    const float* __restrict__ v, float* __restrict__ o)
{
    extern __shared__ float sm[];
    float* Qs = sm;               // [64][68]
    float* Kt = sm + 64*68;       // [d][c] stride 68
    float* Ss = sm + 2*64*68;     // [64][68]
    float* Vs = sm + 3*64*68;     // [64][64]

    int qt = blockIdx.x, bh = blockIdx.y;
    int b = bh >> 4, h = bh & 15;
    int tid = threadIdx.x;
    const float* qb = q + (size_t)b*NT*DIM + h*HD;
    const float* kb = k + (size_t)b*NT*DIM + h*HD;
    const float* vb = v + (size_t)b*NT*DIM + h*HD;

    #pragma unroll
    for (int t = 0; t < 4; t++) {
        int f4 = tid + t*256;
        int row = f4 >> 4, c4 = (f4 & 15)*4;
        float4 qv = *(const float4*)(qb + (size_t)(qt*64+row)*DIM + c4);
        Qs[row*68 + c4+0] = qv.x*0.125f;
        Qs[row*68 + c4+1] = qv.y*0.125f;
        Qs[row*68 + c4+2] = qv.z*0.125f;
        Qs[row*68 + c4+3] = qv.w*0.125f;
    }
    int r  = tid >> 2;
    int cs = (tid & 3)*16;
    float m = -INFINITY, l = 0.f;
    float O[16];
    #pragma unroll
    for (int i = 0; i < 16; i++) O[i] = 0.f;
    __syncthreads();

    for (int kt = 0; kt < NT/64; kt++) {
        #pragma unroll
        for (int t = 0; t < 4; t++) {
            int f4 = tid + t*256;
            int row = f4 >> 4, c4 = (f4 & 15)*4;
            float4 kv = *(const float4*)(kb + (size_t)(kt*64+row)*DIM + c4);
            Kt[(c4+0)*68 + row] = kv.x;
            Kt[(c4+1)*68 + row] = kv.y;
            Kt[(c4+2)*68 + row] = kv.z;
            Kt[(c4+3)*68 + row] = kv.w;
            float4 vv = *(const float4*)(vb + (size_t)(kt*64+row)*DIM + c4);
            *(float4*)&Vs[row*64 + c4] = vv;
        }
        __syncthreads();

        float s[16];
        #pragma unroll
        for (int i = 0; i < 16; i++) s[i] = 0.f;
        #pragma unroll 8
        for (int d = 0; d < 64; d++) {
            float qd = Qs[r*68 + d];
            const float4* kt4 = (const float4*)&Kt[d*68 + cs];
            float4 k0 = kt4[0], k1 = kt4[1], k2 = kt4[2], k3 = kt4[3];
            s[0] += qd*k0.x; s[1] += qd*k0.y; s[2]  += qd*k0.z; s[3]  += qd*k0.w;
            s[4] += qd*k1.x; s[5] += qd*k1.y; s[6]  += qd*k1.z; s[7]  += qd*k1.w;
            s[8] += qd*k2.x; s[9] += qd*k2.y; s[10] += qd*k2.z; s[11] += qd*k2.w;
            s[12]+= qd*k3.x; s[13]+= qd*k3.y; s[14] += qd*k3.z; s[15] += qd*k3.w;
        }
        float tm = s[0];
        #pragma unroll
        for (int i = 1; i < 16; i++) tm = fmaxf(tm, s[i]);
        tm = fmaxf(tm, __shfl_xor_sync(0xffffffffu, tm, 1));
        tm = fmaxf(tm, __shfl_xor_sync(0xffffffffu, tm, 2));
        float mn = fmaxf(m, tm);
        float alpha = __expf(m - mn);
        float rs = 0.f;
        #pragma unroll
        for (int i = 0; i < 16; i++) { s[i] = __expf(s[i]-mn); rs += s[i]; }
        rs += __shfl_xor_sync(0xffffffffu, rs, 1);
        rs += __shfl_xor_sync(0xffffffffu, rs, 2);
        l = l*alpha + rs;
        m = mn;
        #pragma unroll
        for (int i = 0; i < 16; i++) O[i] *= alpha;
        *(float4*)&Ss[r*68+cs+0]  = make_float4(s[0], s[1], s[2], s[3]);
        *(float4*)&Ss[r*68+cs+4]  = make_float4(s[4], s[5], s[6], s[7]);
        *(float4*)&Ss[r*68+cs+8]  = make_float4(s[8], s[9], s[10], s[11]);
        *(float4*)&Ss[r*68+cs+12] = make_float4(s[12], s[13], s[14], s[15]);
        __syncthreads();
        #pragma unroll 8
        for (int j = 0; j < 64; j++) {
            float p = Ss[r*68 + j];
            const float4* v4 = (const float4*)&Vs[j*64 + cs];
            float4 v0 = v4[0], v1 = v4[1], v2 = v4[2], v3 = v4[3];
            O[0] += p*v0.x; O[1] += p*v0.y; O[2]  += p*v0.z; O[3]  += p*v0.w;
            O[4] += p*v1.x; O[5] += p*v1.y; O[6]  += p*v1.z; O[7]  += p*v1.w;
            O[8] += p*v2.x; O[9] += p*v2.y; O[10] += p*v2.z; O[11] += p*v2.w;
            O[12]+= p*v3.x; O[13]+= p*v3.y; O[14] += p*v3.z; O[15] += p*v3.w;
        }
        __syncthreads();
    }
    float inv = 1.f/l;
    float* ob = o + (size_t)(b*NT + qt*64 + r)*DIM + h*HD + cs;
    *(float4*)(ob+0)  = make_float4(O[0]*inv,  O[1]*inv,  O[2]*inv,  O[3]*inv);
    *(float4*)(ob+4)  = make_float4(O[4]*inv,  O[5]*inv,  O[6]*inv,  O[7]*inv);
    *(float4*)(ob+8)  = make_float4(O[8]*inv,  O[9]*inv,  O[10]*inv, O[11]*inv);
    *(float4*)(ob+12) = make_float4(O[12]*inv, O[13]*inv, O[14]*inv, O[15]*inv);
}

// ---------------------------------------------------------------------------
// Host launcher
// ---------------------------------------------------------------------------
extern "C" void kernel_launch(void* const* d_in, const int* in_sizes, int n_in,
                              void* d_out, int out_size)
{
    const float* x       = (const float*)d_in[0];
    const float* t_emb   = (const float*)d_in[1];
    const float* norm1_g = (const float*)d_in[2];
    const float* norm1_b = (const float*)d_in[3];
    const float* Wq      = (const float*)d_in[4];
    const float* Wk      = (const float*)d_in[5];
    const float* Wv      = (const float*)d_in[6];
    const float* Wo      = (const float*)d_in[7];
    const float* norm2_g = (const float*)d_in[8];
    const float* norm2_b = (const float*)d_in[9];
    const float* W1      = (const float*)d_in[10];
    const float* W2      = (const float*)d_in[11];
    const float* ada_W   = (const float*)d_in[12];
    const float* ada_b   = (const float*)d_in[13];
    float* out = (float*)d_out;

    float *mod, *xn, *q, *k, *v, *attn, *hbuf;
    cudaGetSymbolAddress((void**)&mod,  g_mod);
    cudaGetSymbolAddress((void**)&xn,   g_xn);
    cudaGetSymbolAddress((void**)&q,    g_q);
    cudaGetSymbolAddress((void**)&k,    g_k);
    cudaGetSymbolAddress((void**)&v,    g_v);
    cudaGetSymbolAddress((void**)&attn, g_attn);
    cudaGetSymbolAddress((void**)&hbuf, g_h);

    cudaFuncSetAttribute(flash_kernel,
        cudaFuncAttributeMaxDynamicSharedMemorySize, FL_SMEM_BYTES);

    // 1. adaLN modulation
    silu_mod_kernel<<<dim3(24, BT), 256>>>(t_emb, ada_W, ada_b, mod);
    // 2. LN1 + modulate (shift=chunk0, scale=chunk1)
    ln_mod_kernel<<<ROWS, 256>>>(x, xn, norm1_g, norm1_b, mod, 0, 1);
    // 3. QKV projections
    dim3 gQKV(DIM/128, ROWS/128);
    gemm_kernel<0><<<gQKV, 256>>>(xn, Wq, q, ROWS, DIM, DIM, nullptr, nullptr);
    gemm_kernel<0><<<gQKV, 256>>>(xn, Wk, k, ROWS, DIM, DIM, nullptr, nullptr);
    gemm_kernel<0><<<gQKV, 256>>>(xn, Wv, v, ROWS, DIM, DIM, nullptr, nullptr);
    // 4. RoPE on q, k
    rope_kernel<<<(BT*NT*HEADS)/256, 256>>>(q, k);
    // 5. attention
    flash_kernel<<<dim3(NT/64, BT*HEADS), 256, FL_SMEM_BYTES>>>(q, k, v, attn);
    // 6. out proj + gated residual (gate_msa = chunk 2): x1 -> d_out
    gemm_kernel<2><<<gQKV, 256>>>(attn, Wo, out, ROWS, DIM, DIM,
                                  mod + 2*DIM, x);
    // 7. LN2 + modulate (shift=chunk3, scale=chunk4)
    ln_mod_kernel<<<ROWS, 256>>>(out, xn, norm2_g, norm2_b, mod, 3, 4);
    // 8. MLP up + exact GELU
    gemm_kernel<1><<<dim3(MLPD/128, ROWS/128), 256>>>(xn, W1, hbuf,
                                  ROWS, MLPD, DIM, nullptr, nullptr);
    // 9. MLP down + gated residual (gate_mlp = chunk 5): final -> d_out
    gemm_kernel<2><<<gQKV, 256>>>(hbuf, W2, out, ROWS, DIM, MLPD,
                                  mod + 5*DIM, out);
}

// round 6
// speedup vs baseline: 1.0003x; 1.0003x over previous
#include <cuda_runtime.h>
#include <math.h>

#define DIM   1024
#define BT    2
#define NT    2048
#define HEADS 16
#define HD    64
#define MLPD  4096
#define ROWS  (BT*NT)          // 4096 token rows total

// ---------------------------------------------------------------------------
// Scratch (static device globals; runtime allocation is forbidden)
// ---------------------------------------------------------------------------
__device__ float g_mod [BT*6*DIM];     // adaLN modulation (B, 6C)
__device__ float g_xn  [ROWS*DIM];     // LN output (reused for LN1 and LN2)
__device__ float g_q   [ROWS*DIM];
__device__ float g_k   [ROWS*DIM];
__device__ float g_v   [ROWS*DIM];
__device__ float g_attn[ROWS*DIM];     // attention output before Wo
__device__ float g_h   [(size_t)ROWS*MLPD]; // MLP hidden (post-GELU)

// ---------------------------------------------------------------------------
// 1) mod = silu(t_emb) @ ada_W + ada_b        (B,1024)@(1024,6144)
// ---------------------------------------------------------------------------
__global__ void __launch_bounds__(256) silu_mod_kernel(
    const float* __restrict__ t_emb, const float* __restrict__ adaW,
    const float* __restrict__ adab, float* __restrict__ mod)
{
    __shared__ float st[DIM];
    int b = blockIdx.y;
    int j = blockIdx.x * 256 + threadIdx.x;      // 0..6143
    for (int i = threadIdx.x; i < DIM; i += 256) {
        float t = t_emb[b*DIM + i];
        st[i] = t / (1.f + __expf(-t));
    }
    __syncthreads();
    float acc = 0.f;
    #pragma unroll 4
    for (int kk = 0; kk < DIM; kk++)
        acc += st[kk] * adaW[(size_t)kk*6*DIM + j];
    mod[b*6*DIM + j] = acc + adab[j];
}

// ---------------------------------------------------------------------------
// 2) xn = LN(x)*g+b, then * (1+scale_mod) + shift_mod   (one block per row)
// ---------------------------------------------------------------------------
__global__ void __launch_bounds__(256) ln_mod_kernel(
    const float* __restrict__ x, float* __restrict__ out,
    const float* __restrict__ g, const float* __restrict__ bb,
    const float* __restrict__ mod, int shift_chunk, int scale_chunk)
{
    int row = blockIdx.x;
    int b   = row >> 11;                 // row / 2048
    int tid = threadIdx.x;
    const float* xr = x + (size_t)row*DIM;
    float4 xv = *(const float4*)(xr + tid*4);
    float s  = xv.x + xv.y + xv.z + xv.w;
    float s2 = xv.x*xv.x + xv.y*xv.y + xv.z*xv.z + xv.w*xv.w;
    #pragma unroll
    for (int o = 16; o > 0; o >>= 1) {
        s  += __shfl_xor_sync(0xffffffffu, s,  o);
        s2 += __shfl_xor_sync(0xffffffffu, s2, o);
    }
    __shared__ float ws[8], ws2[8];
    __shared__ float smu, srstd;
    int wid = tid >> 5;
    if ((tid & 31) == 0) { ws[wid] = s; ws2[wid] = s2; }
    __syncthreads();
    if (tid == 0) {
        float S = 0.f, S2 = 0.f;
        #pragma unroll
        for (int i = 0; i < 8; i++) { S += ws[i]; S2 += ws2[i]; }
        float mu  = S  * (1.f/DIM);
        float var = S2 * (1.f/DIM) - mu*mu;
        smu = mu; srstd = rsqrtf(var + 1e-5f);
    }
    __syncthreads();
    float mu = smu, rstd = srstd;
    int c = tid*4;
    const float* mb = mod + b*6*DIM;
    float4 gv = *(const float4*)(g  + c);
    float4 bv = *(const float4*)(bb + c);
    float4 sc = *(const float4*)(mb + scale_chunk*DIM + c);
    float4 sh = *(const float4*)(mb + shift_chunk*DIM + c);
    float4 y;
    y.x = ((xv.x-mu)*rstd*gv.x + bv.x)*(1.f+sc.x) + sh.x;
    y.y = ((xv.y-mu)*rstd*gv.y + bv.y)*(1.f+sc.y) + sh.y;
    y.z = ((xv.z-mu)*rstd*gv.z + bv.z)*(1.f+sc.z) + sh.z;
    y.w = ((xv.w-mu)*rstd*gv.w + bv.w)*(1.f+sc.w) + sh.w;
    *(float4*)(out + (size_t)row*DIM + c) = y;
}

// ---------------------------------------------------------------------------
// 3) Tiled SGEMM: Out(M,Nc) = A(M,K) @ W(K,Nc), row-major everywhere.
//    EPI 0: store;  EPI 1: exact GELU;  EPI 2: Out = res + gate[b][col]*acc
//    BM=BN=128, BK=16, 256 threads, 8x8 per thread (split 2x2 of 4x4).
// ---------------------------------------------------------------------------
template<int EPI>
__global__ void __launch_bounds__(256) gemm_kernel(
    const float* __restrict__ A, const float* __restrict__ W,
    float* __restrict__ Out, int M, int Nc, int K,
    const float* __restrict__ gate, const float* __restrict__ res)
{
    __shared__ float As[16][132];    // A tile transposed [k][m], +4 pad
    __shared__ float Bs[16][128];    // W tile [k][n]

    int tid = threadIdx.x;
    int m0 = blockIdx.y * 128;
    int n0 = blockIdx.x * 128;
    int tr4 = (tid >> 4) * 4;        // 0..60
    int tc4 = (tid & 15) * 4;        // 0..60

    int arow = tid >> 2;             // 0..63  (A tile row; +64 second half)
    int ac4  = (tid & 3) * 4;        // 0,4,8,12 (k within tile)
    int brow = tid >> 5;             // 0..7   (W tile k-row; +8 second half)
    int bc4  = (tid & 31) * 4;       // 0..124

    float acc[8][8];
    #pragma unroll
    for (int i = 0; i < 8; i++)
        #pragma unroll
        for (int j = 0; j < 8; j++) acc[i][j] = 0.f;

    for (int k0 = 0; k0 < K; k0 += 16) {
        float4 a0 = *(const float4*)(A + (size_t)(m0+arow)   *K + k0 + ac4);
        float4 a1 = *(const float4*)(A + (size_t)(m0+arow+64)*K + k0 + ac4);
        float4 b0 = *(const float4*)(W + (size_t)(k0+brow)  *Nc + n0 + bc4);
        float4 b1 = *(const float4*)(W + (size_t)(k0+brow+8)*Nc + n0 + bc4);
        __syncthreads();
        As[ac4+0][arow] = a0.x; As[ac4+1][arow] = a0.y;
        As[ac4+2][arow] = a0.z; As[ac4+3][arow] = a0.w;
        As[ac4+0][arow+64] = a1.x; As[ac4+1][arow+64] = a1.y;
        As[ac4+2][arow+64] = a1.z; As[ac4+3][arow+64] = a1.w;
        *(float4*)&Bs[brow  ][bc4] = b0;
        *(float4*)&Bs[brow+8][bc4] = b1;
        __syncthreads();
        #pragma unroll
        for (int kk = 0; kk < 16; kk++) {
            float a[8], bf[8];
            *(float4*)(a)    = *(const float4*)&As[kk][tr4];
            *(float4*)(a+4)  = *(const float4*)&As[kk][tr4+64];
            *(float4*)(bf)   = *(const float4*)&Bs[kk][tc4];
            *(float4*)(bf+4) = *(const float4*)&Bs[kk][tc4+64];
            #pragma unroll
            for (int ii = 0; ii < 8; ii++)
                #pragma unroll
                for (int jj = 0; jj < 8; jj++)
                    acc[ii][jj] += a[ii]*bf[jj];
        }
    }

    #pragma unroll
    for (int ih = 0; ih < 2; ih++) {
        #pragma unroll
        for (int ii = 0; ii < 4; ii++) {
            int row = m0 + tr4 + ih*64 + ii;
            #pragma unroll
            for (int jh = 0; jh < 2; jh++) {
                int col = n0 + tc4 + jh*64;
                float4 vv;
                vv.x = acc[ih*4+ii][jh*4+0];
                vv.y = acc[ih*4+ii][jh*4+1];
                vv.z = acc[ih*4+ii][jh*4+2];
                vv.w = acc[ih*4+ii][jh*4+3];
                if (EPI == 1) {
                    vv.x = 0.5f*vv.x*(1.f + erff(vv.x*0.70710678f));
                    vv.y = 0.5f*vv.y*(1.f + erff(vv.y*0.70710678f));
                    vv.z = 0.5f*vv.z*(1.f + erff(vv.z*0.70710678f));
                    vv.w = 0.5f*vv.w*(1.f + erff(vv.w*0.70710678f));
                } else if (EPI == 2) {
                    int bb = row >> 11;
                    float4 g4 = *(const float4*)(gate + bb*6*DIM + col);
                    float4 r4 = *(const float4*)(res + (size_t)row*Nc + col);
                    vv.x = r4.x + g4.x*vv.x;
                    vv.y = r4.y + g4.y*vv.y;
                    vv.z = r4.z + g4.z*vv.z;
                    vv.w = r4.w + g4.w*vv.w;
                }
                *(float4*)(Out + (size_t)row*Nc + col) = vv;
            }
        }
    }
}

// ---------------------------------------------------------------------------
// 4) RoPE (in-place on q and k). One thread per (b, n, h): 64 contiguous floats.
//    rotate_half: rot[j] = -x[2j+1], rot[32+j] = x[2j]  (j<32)
//    cos/sin index: angle[i] = n * invf[i mod 32]
// ---------------------------------------------------------------------------
__global__ void __launch_bounds__(256) rope_kernel(float* __restrict__ q,
                                                   float* __restrict__ k)
{
    int idx = blockIdx.x*256 + threadIdx.x;          // 0..65535
    int n = (idx >> 4) & (NT-1);                      // token index
    float cs[32], sn[32];
    #pragma unroll
    for (int j = 0; j < 32; j++) {
        float invf = expf((float)j * -0.2878231366f); // -ln(10000)/32
        float ang  = (float)n * invf;
        sincosf(ang, &sn[j], &cs[j]);
    }
    float* ptrs[2]; ptrs[0] = q + (size_t)idx*64; ptrs[1] = k + (size_t)idx*64;
    #pragma unroll
    for (int tpi = 0; tpi < 2; tpi++) {
        float* p = ptrs[tpi];
        float buf[64];
        #pragma unroll
        for (int u = 0; u < 16; u++) {
            float4 t = *(const float4*)(p + u*4);
            buf[u*4+0] = t.x; buf[u*4+1] = t.y; buf[u*4+2] = t.z; buf[u*4+3] = t.w;
        }
        #pragma unroll
        for (int t = 0; t < 8; t++) {
            float4 lo, hi;
            lo.x = buf[4*t+0]*cs[4*t+0] - buf[8*t+1]*sn[4*t+0];
            lo.y = buf[4*t+1]*cs[4*t+1] - buf[8*t+3]*sn[4*t+1];
            lo.z = buf[4*t+2]*cs[4*t+2] - buf[8*t+5]*sn[4*t+2];
            lo.w = buf[4*t+3]*cs[4*t+3] - buf[8*t+7]*sn[4*t+3];
            hi.x = buf[32+4*t+0]*cs[4*t+0] + buf[8*t+0]*sn[4*t+0];
            hi.y = buf[32+4*t+1]*cs[4*t+1] + buf[8*t+2]*sn[4*t+1];
            hi.z = buf[32+4*t+2]*cs[4*t+2] + buf[8*t+4]*sn[4*t+2];
            hi.w = buf[32+4*t+3]*cs[4*t+3] + buf[8*t+6]*sn[4*t+3];
            *(float4*)(p + 4*t)      = lo;
            *(float4*)(p + 32 + 4*t) = hi;
        }
    }
}

// ---------------------------------------------------------------------------
// 5) Flash attention, fp32. Block = (q-tile of 64 rows) x (b,h). 256 threads.
//    Thread owns row r=tid/4 and 16-wide col/dim slice cs=(tid&3)*16.
//    smem: Qs[64][68], Kt[64][68] (d-major), Ss[64][68], Vs[64][64]  = 67 KB
// ---------------------------------------------------------------------------
#define FL_SMEM_FLOATS (3*64*68 + 64*64)
#define FL_SMEM_BYTES  (FL_SMEM_FLOATS*4)

__global__ void __launch_bounds__(256) flash_kernel(
    const float* __restrict__ q, const float* __restrict__ k,
    const float* __restrict__ v, float* __restrict__ o)
{
    extern __shared__ float sm[];
    float* Qs = sm;               // [64][68]
    float* Kt = sm + 64*68;       // [d][c] stride 68
    float* Ss = sm + 2*64*68;     // [64][68]
    float* Vs = sm + 3*64*68;     // [64][64]

    int qt = blockIdx.x, bh = blockIdx.y;
    int b = bh >> 4, h = bh & 15;
    int tid = threadIdx.x;
    const float* qb = q + (size_t)b*NT*DIM + h*HD;
    const float* kb = k + (size_t)b*NT*DIM + h*HD;
    const float* vb = v + (size_t)b*NT*DIM + h*HD;

    #pragma unroll
    for (int t = 0; t < 4; t++) {
        int f4 = tid + t*256;
        int row = f4 >> 4, c4 = (f4 & 15)*4;
        float4 qv = *(const float4*)(qb + (size_t)(qt*64+row)*DIM + c4);
        Qs[row*68 + c4+0] = qv.x*0.125f;
        Qs[row*68 + c4+1] = qv.y*0.125f;
        Qs[row*68 + c4+2] = qv.z*0.125f;
        Qs[row*68 + c4+3] = qv.w*0.125f;
    }
    int r  = tid >> 2;
    int cs = (tid & 3)*16;
    float m = -INFINITY, l = 0.f;
    float O[16];
    #pragma unroll
    for (int i = 0; i < 16; i++) O[i] = 0.f;
    __syncthreads();

    for (int kt = 0; kt < NT/64; kt++) {
        #pragma unroll
        for (int t = 0; t < 4; t++) {
            int f4 = tid + t*256;
            int row = f4 >> 4, c4 = (f4 & 15)*4;
            float4 kv = *(const float4*)(kb + (size_t)(kt*64+row)*DIM + c4);
            Kt[(c4+0)*68 + row] = kv.x;
            Kt[(c4+1)*68 + row] = kv.y;
            Kt[(c4+2)*68 + row] = kv.z;
            Kt[(c4+3)*68 + row] = kv.w;
            float4 vv = *(const float4*)(vb + (size_t)(kt*64+row)*DIM + c4);
            *(float4*)&Vs[row*64 + c4] = vv;
        }
        __syncthreads();

        float s[16];
        #pragma unroll
        for (int i = 0; i < 16; i++) s[i] = 0.f;
        #pragma unroll 8
        for (int d = 0; d < 64; d++) {
            float qd = Qs[r*68 + d];
            const float4* kt4 = (const float4*)&Kt[d*68 + cs];
            float4 k0 = kt4[0], k1 = kt4[1], k2 = kt4[2], k3 = kt4[3];
            s[0] += qd*k0.x; s[1] += qd*k0.y; s[2]  += qd*k0.z; s[3]  += qd*k0.w;
            s[4] += qd*k1.x; s[5] += qd*k1.y; s[6]  += qd*k1.z; s[7]  += qd*k1.w;
            s[8] += qd*k2.x; s[9] += qd*k2.y; s[10] += qd*k2.z; s[11] += qd*k2.w;
            s[12]+= qd*k3.x; s[13]+= qd*k3.y; s[14] += qd*k3.z; s[15] += qd*k3.w;
        }
        float tm = s[0];
        #pragma unroll
        for (int i = 1; i < 16; i++) tm = fmaxf(tm, s[i]);
        tm = fmaxf(tm, __shfl_xor_sync(0xffffffffu, tm, 1));
        tm = fmaxf(tm, __shfl_xor_sync(0xffffffffu, tm, 2));
        float mn = fmaxf(m, tm);
        float alpha = __expf(m - mn);
        float rs = 0.f;
        #pragma unroll
        for (int i = 0; i < 16; i++) { s[i] = __expf(s[i]-mn); rs += s[i]; }
        rs += __shfl_xor_sync(0xffffffffu, rs, 1);
        rs += __shfl_xor_sync(0xffffffffu, rs, 2);
        l = l*alpha + rs;
        m = mn;
        #pragma unroll
        for (int i = 0; i < 16; i++) O[i] *= alpha;
        *(float4*)&Ss[r*68+cs+0]  = make_float4(s[0], s[1], s[2], s[3]);
        *(float4*)&Ss[r*68+cs+4]  = make_float4(s[4], s[5], s[6], s[7]);
        *(float4*)&Ss[r*68+cs+8]  = make_float4(s[8], s[9], s[10], s[11]);
        *(float4*)&Ss[r*68+cs+12] = make_float4(s[12], s[13], s[14], s[15]);
        __syncthreads();
        #pragma unroll 8
        for (int j = 0; j < 64; j++) {
            float p = Ss[r*68 + j];
            const float4* v4 = (const float4*)&Vs[j*64 + cs];
            float4 v0 = v4[0], v1 = v4[1], v2 = v4[2], v3 = v4[3];
            O[0] += p*v0.x; O[1] += p*v0.y; O[2]  += p*v0.z; O[3]  += p*v0.w;
            O[4] += p*v1.x; O[5] += p*v1.y; O[6]  += p*v1.z; O[7]  += p*v1.w;
            O[8] += p*v2.x; O[9] += p*v2.y; O[10] += p*v2.z; O[11] += p*v2.w;
            O[12]+= p*v3.x; O[13]+= p*v3.y; O[14] += p*v3.z; O[15] += p*v3.w;
        }
        __syncthreads();
    }
    float inv = 1.f/l;
    float* ob = o + (size_t)(b*NT + qt*64 + r)*DIM + h*HD + cs;
    *(float4*)(ob+0)  = make_float4(O[0]*inv,  O[1]*inv,  O[2]*inv,  O[3]*inv);
    *(float4*)(ob+4)  = make_float4(O[4]*inv,  O[5]*inv,  O[6]*inv,  O[7]*inv);
    *(float4*)(ob+8)  = make_float4(O[8]*inv,  O[9]*inv,  O[10]*inv, O[11]*inv);
    *(float4*)(ob+12) = make_float4(O[12]*inv, O[13]*inv, O[14]*inv, O[15]*inv);
}

// ---------------------------------------------------------------------------
// Host launcher
// ---------------------------------------------------------------------------
extern "C" void kernel_launch(void* const* d_in, const int* in_sizes, int n_in,
                              void* d_out, int out_size)
{
    const float* x       = (const float*)d_in[0];
    const float* t_emb   = (const float*)d_in[1];
    const float* norm1_g = (const float*)d_in[2];
    const float* norm1_b = (const float*)d_in[3];
    const float* Wq      = (const float*)d_in[4];
    const float* Wk      = (const float*)d_in[5];
    const float* Wv      = (const float*)d_in[6];
    const float* Wo      = (const float*)d_in[7];
    const float* norm2_g = (const float*)d_in[8];
    const float* norm2_b = (const float*)d_in[9];
    const float* W1      = (const float*)d_in[10];
    const float* W2      = (const float*)d_in[11];
    const float* ada_W   = (const float*)d_in[12];
    const float* ada_b   = (const float*)d_in[13];
    float* out = (float*)d_out;

    float *mod, *xn, *q, *k, *v, *attn, *hbuf;
    cudaGetSymbolAddress((void**)&mod,  g_mod);
    cudaGetSymbolAddress((void**)&xn,   g_xn);
    cudaGetSymbolAddress((void**)&q,    g_q);
    cudaGetSymbolAddress((void**)&k,    g_k);
    cudaGetSymbolAddress((void**)&v,    g_v);
    cudaGetSymbolAddress((void**)&attn, g_attn);
    cudaGetSymbolAddress((void**)&hbuf, g_h);

    cudaFuncSetAttribute(flash_kernel,
        cudaFuncAttributeMaxDynamicSharedMemorySize, FL_SMEM_BYTES);

    // 1. adaLN modulation
    silu_mod_kernel<<<dim3(24, BT), 256>>>(t_emb, ada_W, ada_b, mod);
    // 2. LN1 + modulate (shift=chunk0, scale=chunk1)
    ln_mod_kernel<<<ROWS, 256>>>(x, xn, norm1_g, norm1_b, mod, 0, 1);
    // 3. QKV projections
    dim3 gQKV(DIM/128, ROWS/128);
    gemm_kernel<0><<<gQKV, 256>>>(xn, Wq, q, ROWS, DIM, DIM, nullptr, nullptr);
    gemm_kernel<0><<<gQKV, 256>>>(xn, Wk, k, ROWS, DIM, DIM, nullptr, nullptr);
    gemm_kernel<0><<<gQKV, 256>>>(xn, Wv, v, ROWS, DIM, DIM, nullptr, nullptr);
    // 4. RoPE on q, k
    rope_kernel<<<(BT*NT*HEADS)/256, 256>>>(q, k);
    // 5. attention
    flash_kernel<<<dim3(NT/64, BT*HEADS), 256, FL_SMEM_BYTES>>>(q, k, v, attn);
    // 6. out proj + gated residual (gate_msa = chunk 2): x1 -> d_out
    gemm_kernel<2><<<gQKV, 256>>>(attn, Wo, out, ROWS, DIM, DIM,
                                  mod + 2*DIM, x);
    // 7. LN2 + modulate (shift=chunk3, scale=chunk4)
    ln_mod_kernel<<<ROWS, 256>>>(out, xn, norm2_g, norm2_b, mod, 3, 4);
    // 8. MLP up + exact GELU
    gemm_kernel<1><<<dim3(MLPD/128, ROWS/128), 256>>>(xn, W1, hbuf,
                                  ROWS, MLPD, DIM, nullptr, nullptr);
    // 9. MLP down + gated residual (gate_mlp = chunk 5): final -> d_out
    gemm_kernel<2><<<gQKV, 256>>>(hbuf, W2, out, ROWS, DIM, MLPD,
                                  mod + 5*DIM, out);
}

// round 7
// speedup vs baseline: 4.8404x; 4.8392x over previous
#include <cuda_runtime.h>
#include <math.h>
#include <stdint.h>

#define DIM   1024
#define BT    2
#define NT    2048
#define HEADS 16
#define HD    64
#define MLPD  4096
#define ROWS  (BT*NT)          // 4096 token rows total

// ---------------------------------------------------------------------------
// Scratch (static device globals; runtime allocation is forbidden)
// ---------------------------------------------------------------------------
__device__ float g_mod [BT*6*DIM];
__device__ float g_xn  [ROWS*DIM];
__device__ float g_q   [ROWS*DIM];
__device__ float g_k   [ROWS*DIM];
__device__ float g_v   [ROWS*DIM];
__device__ float g_attn[ROWS*DIM];
__device__ float g_h   [(size_t)ROWS*MLPD];

// ---------------------------------------------------------------------------
// PTX helpers
// ---------------------------------------------------------------------------
__device__ __forceinline__ uint32_t smaddr(const void* p){
    return (uint32_t)__cvta_generic_to_shared(p);
}
__device__ __forceinline__ void cp16(uint32_t d, const void* s){
    asm volatile("cp.async.cg.shared.global [%0], [%1], 16;\n" :: "r"(d), "l"(s));
}
__device__ __forceinline__ void cp_commit(){
    asm volatile("cp.async.commit_group;\n" ::);
}
__device__ __forceinline__ void cp_wait1(){
    asm volatile("cp.async.wait_group 1;\n" ::);
}
// Round-to-nearest fp32 -> tf32 (kills the RZ truncation bias of raw mma feed)
__device__ __forceinline__ float to_tf32(float x){
    float r;
    asm volatile("cvt.rna.tf32.f32 %0, %1;\n" : "=f"(r) : "f"(x));
    return r;
}
// D(16x8) += A(16x8,row) * B(8x8,col), tf32 inputs, f32 accumulate
__device__ __forceinline__ void mma16n8k8(float* c, const float* a, const float* b){
    asm volatile(
        "mma.sync.aligned.m16n8k8.row.col.f32.tf32.tf32.f32 "
        "{%0,%1,%2,%3}, {%4,%5,%6,%7}, {%8,%9}, {%0,%1,%2,%3};\n"
        : "+f"(c[0]), "+f"(c[1]), "+f"(c[2]), "+f"(c[3])
        : "r"(__float_as_uint(a[0])), "r"(__float_as_uint(a[1])),
          "r"(__float_as_uint(a[2])), "r"(__float_as_uint(a[3])),
          "r"(__float_as_uint(b[0])), "r"(__float_as_uint(b[1])));
}

// ---------------------------------------------------------------------------
// 1) mod = silu(t_emb) @ ada_W + ada_b
// ---------------------------------------------------------------------------
__global__ void __launch_bounds__(256) silu_mod_kernel(
    const float* __restrict__ t_emb, const float* __restrict__ adaW,
    const float* __restrict__ adab, float* __restrict__ mod)
{
    __shared__ float st[DIM];
    int b = blockIdx.y;
    int j = blockIdx.x * 256 + threadIdx.x;
    for (int i = threadIdx.x; i < DIM; i += 256) {
        float t = t_emb[b*DIM + i];
        st[i] = t / (1.f + __expf(-t));
    }
    __syncthreads();
    float acc = 0.f;
    #pragma unroll 4
    for (int kk = 0; kk < DIM; kk++)
        acc += st[kk] * adaW[(size_t)kk*6*DIM + j];
    mod[b*6*DIM + j] = acc + adab[j];
}

// ---------------------------------------------------------------------------
// 2) LN + adaLN modulation (one block per row)
// ---------------------------------------------------------------------------
__global__ void __launch_bounds__(256) ln_mod_kernel(
    const float* __restrict__ x, float* __restrict__ out,
    const float* __restrict__ g, const float* __restrict__ bb,
    const float* __restrict__ mod, int shift_chunk, int scale_chunk)
{
    int row = blockIdx.x;
    int b   = row >> 11;
    int tid = threadIdx.x;
    const float* xr = x + (size_t)row*DIM;
    float4 xv = *(const float4*)(xr + tid*4);
    float s  = xv.x + xv.y + xv.z + xv.w;
    float s2 = xv.x*xv.x + xv.y*xv.y + xv.z*xv.z + xv.w*xv.w;
    #pragma unroll
    for (int o = 16; o > 0; o >>= 1) {
        s  += __shfl_xor_sync(0xffffffffu, s,  o);
        s2 += __shfl_xor_sync(0xffffffffu, s2, o);
    }
    __shared__ float ws[8], ws2[8];
    __shared__ float smu, srstd;
    int wid = tid >> 5;
    if ((tid & 31) == 0) { ws[wid] = s; ws2[wid] = s2; }
    __syncthreads();
    if (tid == 0) {
        float S = 0.f, S2 = 0.f;
        #pragma unroll
        for (int i = 0; i < 8; i++) { S += ws[i]; S2 += ws2[i]; }
        float mu  = S  * (1.f/DIM);
        float var = S2 * (1.f/DIM) - mu*mu;
        smu = mu; srstd = rsqrtf(var + 1e-5f);
    }
    __syncthreads();
    float mu = smu, rstd = srstd;
    int c = tid*4;
    const float* mb = mod + b*6*DIM;
    float4 gv = *(const float4*)(g  + c);
    float4 bv = *(const float4*)(bb + c);
    float4 sc = *(const float4*)(mb + scale_chunk*DIM + c);
    float4 sh = *(const float4*)(mb + shift_chunk*DIM + c);
    float4 y;
    y.x = ((xv.x-mu)*rstd*gv.x + bv.x)*(1.f+sc.x) + sh.x;
    y.y = ((xv.y-mu)*rstd*gv.y + bv.y)*(1.f+sc.y) + sh.y;
    y.z = ((xv.z-mu)*rstd*gv.z + bv.z)*(1.f+sc.z) + sh.z;
    y.w = ((xv.w-mu)*rstd*gv.w + bv.w)*(1.f+sc.w) + sh.w;
    *(float4*)(out + (size_t)row*DIM + c) = y;
}

// ---------------------------------------------------------------------------
// 3) TF32 tensor-core GEMM: Out(M,Nc) = A(M,K) @ W(K,Nc), row-major.
//    BM=BN=128, BK=32. 256 thr = 8 warps (4 along M x 2 along N), warp 32x64.
//    cp.async double-buffered smem. EPI: 0 store, 1 GELU, 2 res+gate*acc.
//    Smem: As[128][36] (pad->bank 4g+t), Bs[32][136] (pad->bank 8t+g), x2 buf.
// ---------------------------------------------------------------------------
#define G_ABUF 4608            // 128*36 floats
#define G_BBUF 4352            // 32*136 floats
#define G_BUF  (G_ABUF + G_BBUF)
#define G_SMEM_BYTES (2*G_BUF*4)

template<int EPI>
__global__ void __launch_bounds__(256) gemm_tc(
    const float* __restrict__ A, const float* __restrict__ W,
    float* __restrict__ Out, int M, int Nc, int K,
    const float* __restrict__ gate, const float* __restrict__ res)
{
    extern __shared__ float sm[];
    const int tid  = threadIdx.x;
    const int lane = tid & 31, warp = tid >> 5;
    const int grp  = lane >> 2, tig = lane & 3;
    const int wm   = warp & 3,  wn  = warp >> 2;
    const int m0   = blockIdx.y * 128, n0 = blockIdx.x * 128;
    const uint32_t smb = smaddr(sm);
    const int nk = K >> 5;

    float acc[2][8][4];
    #pragma unroll
    for (int i = 0; i < 2; i++)
        #pragma unroll
        for (int j = 0; j < 8; j++)
            #pragma unroll
            for (int t = 0; t < 4; t++) acc[i][j][t] = 0.f;

    auto prefetch = [&](int kc, int bufi){
        int off = bufi * G_BUF;
        #pragma unroll
        for (int i = 0; i < 4; i++) {
            int idx = tid + i*256;
            int r = idx >> 3, c4 = (idx & 7) * 4;
            cp16(smb + (uint32_t)(off + r*36 + c4)*4u,
                 A + (size_t)(m0 + r)*K + kc*32 + c4);
        }
        #pragma unroll
        for (int i = 0; i < 4; i++) {
            int idx = tid + i*256;
            int r = idx >> 5, c4 = (idx & 31) * 4;
            cp16(smb + (uint32_t)(off + G_ABUF + r*136 + c4)*4u,
                 W + (size_t)(kc*32 + r)*Nc + n0 + c4);
        }
    };

    prefetch(0, 0); cp_commit();
    int buf = 0;
    for (int kc = 0; kc < nk; kc++) {
        if (kc + 1 < nk) prefetch(kc + 1, buf ^ 1);
        cp_commit();
        cp_wait1();
        __syncthreads();
        const float* As = sm + buf*G_BUF;
        const float* Bs = As + G_ABUF;
        #pragma unroll
        for (int kk = 0; kk < 32; kk += 8) {
            float af[2][4], bf[8][2];
            #pragma unroll
            for (int ma = 0; ma < 2; ma++) {
                int r = wm*32 + ma*16 + grp;
                af[ma][0] = to_tf32(As[r    *36 + kk + tig]);
                af[ma][1] = to_tf32(As[(r+8)*36 + kk + tig]);
                af[ma][2] = to_tf32(As[r    *36 + kk + tig + 4]);
                af[ma][3] = to_tf32(As[(r+8)*36 + kk + tig + 4]);
            }
            #pragma unroll
            for (int nb = 0; nb < 8; nb++) {
                int c = wn*64 + nb*8 + grp;
                bf[nb][0] = to_tf32(Bs[(kk+tig  )*136 + c]);
                bf[nb][1] = to_tf32(Bs[(kk+tig+4)*136 + c]);
            }
            #pragma unroll
            for (int ma = 0; ma < 2; ma++)
                #pragma unroll
                for (int nb = 0; nb < 8; nb++)
                    mma16n8k8(acc[ma][nb], af[ma], bf[nb]);
        }
        __syncthreads();
        buf ^= 1;
    }

    // epilogue: c0,c1 at (row, 2t/2t+1), c2,c3 at (row+8, ...)
    #pragma unroll
    for (int ma = 0; ma < 2; ma++) {
        int r0 = m0 + wm*32 + ma*16 + grp;
        #pragma unroll
        for (int nb = 0; nb < 8; nb++) {
            int c = n0 + wn*64 + nb*8 + 2*tig;
            float o0 = acc[ma][nb][0], o1 = acc[ma][nb][1];
            float o2 = acc[ma][nb][2], o3 = acc[ma][nb][3];
            if (EPI == 1) {
                o0 = 0.5f*o0*(1.f + erff(o0*0.70710678f));
                o1 = 0.5f*o1*(1.f + erff(o1*0.70710678f));
                o2 = 0.5f*o2*(1.f + erff(o2*0.70710678f));
                o3 = 0.5f*o3*(1.f + erff(o3*0.70710678f));
            } else if (EPI == 2) {
                int bi = r0 >> 11;
                float2 g2 = *(const float2*)(gate + bi*6*DIM + c);
                float2 ra = *(const float2*)(res + (size_t)r0    *Nc + c);
                float2 rb = *(const float2*)(res + (size_t)(r0+8)*Nc + c);
                o0 = ra.x + g2.x*o0; o1 = ra.y + g2.y*o1;
                o2 = rb.x + g2.x*o2; o3 = rb.y + g2.y*o3;
            }
            *(float2*)(Out + (size_t)r0    *Nc + c) = make_float2(o0, o1);
            *(float2*)(Out + (size_t)(r0+8)*Nc + c) = make_float2(o2, o3);
        }
    }
}

// ---------------------------------------------------------------------------
// 4) RoPE (unchanged)
// ---------------------------------------------------------------------------
__global__ void __launch_bounds__(256) rope_kernel(float* __restrict__ q,
                                                   float* __restrict__ k)
{
    int idx = blockIdx.x*256 + threadIdx.x;
    int n = (idx >> 4) & (NT-1);
    float cs[32], sn[32];
    #pragma unroll
    for (int j = 0; j < 32; j++) {
        float invf = expf((float)j * -0.2878231366f);
        float ang  = (float)n * invf;
        sincosf(ang, &sn[j], &cs[j]);
    }
    float* ptrs[2]; ptrs[0] = q + (size_t)idx*64; ptrs[1] = k + (size_t)idx*64;
    #pragma unroll
    for (int tpi = 0; tpi < 2; tpi++) {
        float* p = ptrs[tpi];
        float buf[64];
        #pragma unroll
        for (int u = 0; u < 16; u++) {
            float4 t = *(const float4*)(p + u*4);
            buf[u*4+0] = t.x; buf[u*4+1] = t.y; buf[u*4+2] = t.z; buf[u*4+3] = t.w;
        }
        #pragma unroll
        for (int t = 0; t < 8; t++) {
            float4 lo, hi;
            lo.x = buf[4*t+0]*cs[4*t+0] - buf[8*t+1]*sn[4*t+0];
            lo.y = buf[4*t+1]*cs[4*t+1] - buf[8*t+3]*sn[4*t+1];
            lo.z = buf[4*t+2]*cs[4*t+2] - buf[8*t+5]*sn[4*t+2];
            lo.w = buf[4*t+3]*cs[4*t+3] - buf[8*t+7]*sn[4*t+3];
            hi.x = buf[32+4*t+0]*cs[4*t+0] + buf[8*t+0]*sn[4*t+0];
            hi.y = buf[32+4*t+1]*cs[4*t+1] + buf[8*t+2]*sn[4*t+1];
            hi.z = buf[32+4*t+2]*cs[4*t+2] + buf[8*t+4]*sn[4*t+2];
            hi.w = buf[32+4*t+3]*cs[4*t+3] + buf[8*t+6]*sn[4*t+3];
            *(float4*)(p + 4*t)      = lo;
            *(float4*)(p + 32 + 4*t) = hi;
        }
    }
}

// ---------------------------------------------------------------------------
// 5) Flash attention with tf32 mma. CTA = 64-row Q tile, 4 warps x 16 rows.
//    Register-resident S and O; online softmax in registers (quad shfl);
//    P via smem (warp-private rows -> __syncwarp only).
//    Smem: Qs[64][68] Ks[64][68] Vs[64][72] Ps[64][68]  (~69 KB)
// ---------------------------------------------------------------------------
#define F_QS 0
#define F_KS 4352
#define F_VS 8704
#define F_PS 13312
#define F_SMEM_BYTES (17664*4)

__global__ void __launch_bounds__(128) flash_tc(
    const float* __restrict__ q, const float* __restrict__ k,
    const float* __restrict__ v, float* __restrict__ o)
{
    extern __shared__ float sm[];
    float* Qs = sm + F_QS;
    float* Ks = sm + F_KS;
    float* Vs = sm + F_VS;
    float* Ps = sm + F_PS;

    const int qt = blockIdx.x, bh = blockIdx.y;
    const int b = bh >> 4, h = bh & 15;
    const int tid = threadIdx.x;
    const int lane = tid & 31, warp = tid >> 5;
    const int grp = lane >> 2, tig = lane & 3;
    const int wrow = warp * 16;
    const float* qb = q + (size_t)b*NT*DIM + h*HD;
    const float* kb = k + (size_t)b*NT*DIM + h*HD;
    const float* vb = v + (size_t)b*NT*DIM + h*HD;

    // Q tile: scale by 1/sqrt(D) (exact pow2) then round to tf32
    #pragma unroll
    for (int i = 0; i < 8; i++) {
        int idx = tid + i*128;
        int r = idx >> 4, c4 = (idx & 15) * 4;
        float4 t = *(const float4*)(qb + (size_t)(qt*64 + r)*DIM + c4);
        t.x = to_tf32(t.x*0.125f); t.y = to_tf32(t.y*0.125f);
        t.z = to_tf32(t.z*0.125f); t.w = to_tf32(t.w*0.125f);
        *(float4*)(Qs + r*68 + c4) = t;
    }

    float O[8][4];
    #pragma unroll
    for (int i = 0; i < 8; i++)
        #pragma unroll
        for (int j = 0; j < 4; j++) O[i][j] = 0.f;
    float m0 = -1e30f, m1 = -1e30f, l0 = 0.f, l1 = 0.f;

    for (int kt = 0; kt < NT/64; kt++) {
        __syncthreads();           // prev tile reads done before overwrite
        float4 kf[8], vf[8];
        #pragma unroll
        for (int i = 0; i < 8; i++) {
            int idx = tid + i*128;
            int r = idx >> 4, c4 = (idx & 15) * 4;
            kf[i] = *(const float4*)(kb + (size_t)(kt*64 + r)*DIM + c4);
            vf[i] = *(const float4*)(vb + (size_t)(kt*64 + r)*DIM + c4);
        }
        #pragma unroll
        for (int i = 0; i < 8; i++) {
            int idx = tid + i*128;
            int r = idx >> 4, c4 = (idx & 15) * 4;
            float4 t = kf[i];
            t.x = to_tf32(t.x); t.y = to_tf32(t.y);
            t.z = to_tf32(t.z); t.w = to_tf32(t.w);
            *(float4*)(Ks + r*68 + c4) = t;
            t = vf[i];
            t.x = to_tf32(t.x); t.y = to_tf32(t.y);
            t.z = to_tf32(t.z); t.w = to_tf32(t.w);
            *(float4*)(Vs + r*72 + c4) = t;
        }
        __syncthreads();

        // S = Q @ K^T   (16x64 per warp)
        float s[8][4];
        #pragma unroll
        for (int i = 0; i < 8; i++)
            #pragma unroll
            for (int j = 0; j < 4; j++) s[i][j] = 0.f;
        #pragma unroll
        for (int kk = 0; kk < 64; kk += 8) {
            float af[4];
            af[0] = Qs[(wrow+grp  )*68 + kk + tig];
            af[1] = Qs[(wrow+grp+8)*68 + kk + tig];
            af[2] = Qs[(wrow+grp  )*68 + kk + tig + 4];
            af[3] = Qs[(wrow+grp+8)*68 + kk + tig + 4];
            #pragma unroll
            for (int nb = 0; nb < 8; nb++) {
                float bf[2];
                bf[0] = Ks[(nb*8+grp)*68 + kk + tig];
                bf[1] = Ks[(nb*8+grp)*68 + kk + tig + 4];
                mma16n8k8(s[nb], af, bf);
            }
        }

        // online softmax (rows grp and grp+8 of this warp's 16)
        float mx0 = -1e30f, mx1 = -1e30f;
        #pragma unroll
        for (int nb = 0; nb < 8; nb++) {
            mx0 = fmaxf(mx0, fmaxf(s[nb][0], s[nb][1]));
            mx1 = fmaxf(mx1, fmaxf(s[nb][2], s[nb][3]));
        }
        mx0 = fmaxf(mx0, __shfl_xor_sync(0xffffffffu, mx0, 1));
        mx0 = fmaxf(mx0, __shfl_xor_sync(0xffffffffu, mx0, 2));
        mx1 = fmaxf(mx1, __shfl_xor_sync(0xffffffffu, mx1, 1));
        mx1 = fmaxf(mx1, __shfl_xor_sync(0xffffffffu, mx1, 2));
        float nm0 = fmaxf(m0, mx0), nm1 = fmaxf(m1, mx1);
        float a0 = __expf(m0 - nm0), a1 = __expf(m1 - nm1);
        float rs0 = 0.f, rs1 = 0.f;
        #pragma unroll
        for (int nb = 0; nb < 8; nb++) {
            float p0 = to_tf32(__expf(s[nb][0] - nm0));
            float p1 = to_tf32(__expf(s[nb][1] - nm0));
            float p2 = to_tf32(__expf(s[nb][2] - nm1));
            float p3 = to_tf32(__expf(s[nb][3] - nm1));
            rs0 += p0 + p1; rs1 += p2 + p3;
            *(float2*)(Ps + (wrow+grp  )*68 + nb*8 + 2*tig) = make_float2(p0, p1);
            *(float2*)(Ps + (wrow+grp+8)*68 + nb*8 + 2*tig) = make_float2(p2, p3);
            O[nb][0] *= a0; O[nb][1] *= a0;
            O[nb][2] *= a1; O[nb][3] *= a1;
        }
        rs0 += __shfl_xor_sync(0xffffffffu, rs0, 1);
        rs0 += __shfl_xor_sync(0xffffffffu, rs0, 2);
        rs1 += __shfl_xor_sync(0xffffffffu, rs1, 1);
        rs1 += __shfl_xor_sync(0xffffffffu, rs1, 2);
        l0 = l0*a0 + rs0; l1 = l1*a1 + rs1;
        m0 = nm0; m1 = nm1;
        __syncwarp();   // P rows are warp-private: warp-level barrier suffices

        // O += P @ V
        #pragma unroll
        for (int kk = 0; kk < 64; kk += 8) {
            float af[4];
            af[0] = Ps[(wrow+grp  )*68 + kk + tig];
            af[1] = Ps[(wrow+grp+8)*68 + kk + tig];
            af[2] = Ps[(wrow+grp  )*68 + kk + tig + 4];
            af[3] = Ps[(wrow+grp+8)*68 + kk + tig + 4];
            #pragma unroll
            for (int nb = 0; nb < 8; nb++) {
                float bf[2];
                bf[0] = Vs[(kk+tig  )*72 + nb*8 + grp];
                bf[1] = Vs[(kk+tig+4)*72 + nb*8 + grp];
                mma16n8k8(O[nb], af, bf);
            }
        }
        __syncwarp();
    }

    float i0 = 1.f/l0, i1 = 1.f/l1;
    int row = qt*64 + wrow + grp;
    #pragma unroll
    for (int nb = 0; nb < 8; nb++) {
        float* op = o + (size_t)(b*NT + row)*DIM + h*HD + nb*8 + 2*tig;
        *(float2*)op            = make_float2(O[nb][0]*i0, O[nb][1]*i0);
        *(float2*)(op + 8*DIM)  = make_float2(O[nb][2]*i1, O[nb][3]*i1);
    }
}

// ---------------------------------------------------------------------------
// Host launcher
// ---------------------------------------------------------------------------
extern "C" void kernel_launch(void* const* d_in, const int* in_sizes, int n_in,
                              void* d_out, int out_size)
{
    const float* x       = (const float*)d_in[0];
    const float* t_emb   = (const float*)d_in[1];
    const float* norm1_g = (const float*)d_in[2];
    const float* norm1_b = (const float*)d_in[3];
    const float* Wq      = (const float*)d_in[4];
    const float* Wk      = (const float*)d_in[5];
    const float* Wv      = (const float*)d_in[6];
    const float* Wo      = (const float*)d_in[7];
    const float* norm2_g = (const float*)d_in[8];
    const float* norm2_b = (const float*)d_in[9];
    const float* W1      = (const float*)d_in[10];
    const float* W2      = (const float*)d_in[11];
    const float* ada_W   = (const float*)d_in[12];
    const float* ada_b   = (const float*)d_in[13];
    float* out = (float*)d_out;

    float *mod, *xn, *q, *k, *v, *attn, *hbuf;
    cudaGetSymbolAddress((void**)&mod,  g_mod);
    cudaGetSymbolAddress((void**)&xn,   g_xn);
    cudaGetSymbolAddress((void**)&q,    g_q);
    cudaGetSymbolAddress((void**)&k,    g_k);
    cudaGetSymbolAddress((void**)&v,    g_v);
    cudaGetSymbolAddress((void**)&attn, g_attn);
    cudaGetSymbolAddress((void**)&hbuf, g_h);

    cudaFuncSetAttribute(gemm_tc<0>,
        cudaFuncAttributeMaxDynamicSharedMemorySize, G_SMEM_BYTES);
    cudaFuncSetAttribute(gemm_tc<1>,
        cudaFuncAttributeMaxDynamicSharedMemorySize, G_SMEM_BYTES);
    cudaFuncSetAttribute(gemm_tc<2>,
        cudaFuncAttributeMaxDynamicSharedMemorySize, G_SMEM_BYTES);
    cudaFuncSetAttribute(flash_tc,
        cudaFuncAttributeMaxDynamicSharedMemorySize, F_SMEM_BYTES);

    // 1. adaLN modulation
    silu_mod_kernel<<<dim3(24, BT), 256>>>(t_emb, ada_W, ada_b, mod);
    // 2. LN1 + modulate (shift=0, scale=1)
    ln_mod_kernel<<<ROWS, 256>>>(x, xn, norm1_g, norm1_b, mod, 0, 1);
    // 3. QKV projections (tf32 TC)
    dim3 gQKV(DIM/128, ROWS/128);
    gemm_tc<0><<<gQKV, 256, G_SMEM_BYTES>>>(xn, Wq, q, ROWS, DIM, DIM, nullptr, nullptr);
    gemm_tc<0><<<gQKV, 256, G_SMEM_BYTES>>>(xn, Wk, k, ROWS, DIM, DIM, nullptr, nullptr);
    gemm_tc<0><<<gQKV, 256, G_SMEM_BYTES>>>(xn, Wv, v, ROWS, DIM, DIM, nullptr, nullptr);
    // 4. RoPE
    rope_kernel<<<(BT*NT*HEADS)/256, 256>>>(q, k);
    // 5. attention (tf32 TC flash)
    flash_tc<<<dim3(NT/64, BT*HEADS), 128, F_SMEM_BYTES>>>(q, k, v, attn);
    // 6. out proj + gated residual (gate_msa = chunk 2) -> d_out
    gemm_tc<2><<<gQKV, 256, G_SMEM_BYTES>>>(attn, Wo, out, ROWS, DIM, DIM,
                                            mod + 2*DIM, x);
    // 7. LN2 + modulate (shift=3, scale=4)
    ln_mod_kernel<<<ROWS, 256>>>(out, xn, norm2_g, norm2_b, mod, 3, 4);
    // 8. MLP up + exact GELU
    gemm_tc<1><<<dim3(MLPD/128, ROWS/128), 256, G_SMEM_BYTES>>>(
        xn, W1, hbuf, ROWS, MLPD, DIM, nullptr, nullptr);
    // 9. MLP down + gated residual (gate_mlp = chunk 5) -> d_out
    gemm_tc<2><<<gQKV, 256, G_SMEM_BYTES>>>(hbuf, W2, out, ROWS, DIM, MLPD,
                                            mod + 5*DIM, out);
}

// round 8
// speedup vs baseline: 5.3781x; 1.1111x over previous
#include <cuda_runtime.h>
#include <math.h>
#include <stdint.h>

#define DIM   1024
#define BT    2
#define NT    2048
#define HEADS 16
#define HD    64
#define MLPD  4096
#define ROWS  (BT*NT)

// ---------------------------------------------------------------------------
// Scratch (static device globals)
// ---------------------------------------------------------------------------
__device__ float g_mod [BT*6*DIM];
__device__ float g_xn  [ROWS*DIM];
__device__ float g_q   [ROWS*DIM];
__device__ float g_k   [ROWS*DIM];
__device__ float g_v   [ROWS*DIM];
__device__ float g_attn[ROWS*DIM];
__device__ float g_h   [(size_t)ROWS*MLPD];
// pre-rounded (tf32) weights: Wq,Wk,Wv,Wo (1M each), W1 (4M), W2 (4M)
__device__ float g_wt  [12*1024*1024];

// ---------------------------------------------------------------------------
// PTX helpers
// ---------------------------------------------------------------------------
__device__ __forceinline__ uint32_t smaddr(const void* p){
    return (uint32_t)__cvta_generic_to_shared(p);
}
__device__ __forceinline__ void cp16(uint32_t d, const void* s){
    asm volatile("cp.async.cg.shared.global [%0], [%1], 16;\n" :: "r"(d), "l"(s));
}
__device__ __forceinline__ void cp_commit(){
    asm volatile("cp.async.commit_group;\n" ::);
}
__device__ __forceinline__ void cp_wait1(){
    asm volatile("cp.async.wait_group 1;\n" ::);
}
__device__ __forceinline__ float to_tf32(float x){
    float r;
    asm volatile("cvt.rna.tf32.f32 %0, %1;\n" : "=f"(r) : "f"(x));
    return r;
}
__device__ __forceinline__ void mma16n8k8(float* c, const float* a, const float* b){
    asm volatile(
        "mma.sync.aligned.m16n8k8.row.col.f32.tf32.tf32.f32 "
        "{%0,%1,%2,%3}, {%4,%5,%6,%7}, {%8,%9}, {%0,%1,%2,%3};\n"
        : "+f"(c[0]), "+f"(c[1]), "+f"(c[2]), "+f"(c[3])
        : "r"(__float_as_uint(a[0])), "r"(__float_as_uint(a[1])),
          "r"(__float_as_uint(a[2])), "r"(__float_as_uint(a[3])),
          "r"(__float_as_uint(b[0])), "r"(__float_as_uint(b[1])));
}

// ---------------------------------------------------------------------------
// 0) Pre-round a float array to tf32 (vectorized)
// ---------------------------------------------------------------------------
__global__ void __launch_bounds__(256) round_tf32_kernel(
    const float* __restrict__ in, float* __restrict__ out, int n4)
{
    int i = blockIdx.x*256 + threadIdx.x;
    if (i < n4) {
        float4 t = ((const float4*)in)[i];
        t.x = to_tf32(t.x); t.y = to_tf32(t.y);
        t.z = to_tf32(t.z); t.w = to_tf32(t.w);
        ((float4*)out)[i] = t;
    }
}

// ---------------------------------------------------------------------------
// 1) mod = silu(t_emb) @ ada_W + ada_b
// ---------------------------------------------------------------------------
__global__ void __launch_bounds__(256) silu_mod_kernel(
    const float* __restrict__ t_emb, const float* __restrict__ adaW,
    const float* __restrict__ adab, float* __restrict__ mod)
{
    __shared__ float st[DIM];
    int b = blockIdx.y;
    int j = blockIdx.x * 256 + threadIdx.x;
    for (int i = threadIdx.x; i < DIM; i += 256) {
        float t = t_emb[b*DIM + i];
        st[i] = t / (1.f + __expf(-t));
    }
    __syncthreads();
    float acc = 0.f;
    #pragma unroll 4
    for (int kk = 0; kk < DIM; kk++)
        acc += st[kk] * adaW[(size_t)kk*6*DIM + j];
    mod[b*6*DIM + j] = acc + adab[j];
}

// ---------------------------------------------------------------------------
// 2) LN + adaLN modulation; output tf32-rounded (feeds MMA only)
// ---------------------------------------------------------------------------
__global__ void __launch_bounds__(256) ln_mod_kernel(
    const float* __restrict__ x, float* __restrict__ out,
    const float* __restrict__ g, const float* __restrict__ bb,
    const float* __restrict__ mod, int shift_chunk, int scale_chunk)
{
    int row = blockIdx.x;
    int b   = row >> 11;
    int tid = threadIdx.x;
    const float* xr = x + (size_t)row*DIM;
    float4 xv = *(const float4*)(xr + tid*4);
    float s  = xv.x + xv.y + xv.z + xv.w;
    float s2 = xv.x*xv.x + xv.y*xv.y + xv.z*xv.z + xv.w*xv.w;
    #pragma unroll
    for (int o = 16; o > 0; o >>= 1) {
        s  += __shfl_xor_sync(0xffffffffu, s,  o);
        s2 += __shfl_xor_sync(0xffffffffu, s2, o);
    }
    __shared__ float ws[8], ws2[8];
    __shared__ float smu, srstd;
    int wid = tid >> 5;
    if ((tid & 31) == 0) { ws[wid] = s; ws2[wid] = s2; }
    __syncthreads();
    if (tid == 0) {
        float S = 0.f, S2 = 0.f;
        #pragma unroll
        for (int i = 0; i < 8; i++) { S += ws[i]; S2 += ws2[i]; }
        float mu  = S  * (1.f/DIM);
        float var = S2 * (1.f/DIM) - mu*mu;
        smu = mu; srstd = rsqrtf(var + 1e-5f);
    }
    __syncthreads();
    float mu = smu, rstd = srstd;
    int c = tid*4;
    const float* mb = mod + b*6*DIM;
    float4 gv = *(const float4*)(g  + c);
    float4 bv = *(const float4*)(bb + c);
    float4 sc = *(const float4*)(mb + scale_chunk*DIM + c);
    float4 sh = *(const float4*)(mb + shift_chunk*DIM + c);
    float4 y;
    y.x = to_tf32(((xv.x-mu)*rstd*gv.x + bv.x)*(1.f+sc.x) + sh.x);
    y.y = to_tf32(((xv.y-mu)*rstd*gv.y + bv.y)*(1.f+sc.y) + sh.y);
    y.z = to_tf32(((xv.z-mu)*rstd*gv.z + bv.z)*(1.f+sc.z) + sh.z);
    y.w = to_tf32(((xv.w-mu)*rstd*gv.w + bv.w)*(1.f+sc.w) + sh.w);
    *(float4*)(out + (size_t)row*DIM + c) = y;
}

// ---------------------------------------------------------------------------
// GEMM core pieces (shared by gemm_tc and gemm_qkv)
//    BM=BN=128, BK=32, 256 thr = 8 warps (4 M x 2 N), warp 32x64.
//    All operands pre-rounded tf32 -> no cvt in inner loop.
// ---------------------------------------------------------------------------
#define G_ABUF 4608            // 128*36 floats
#define G_BBUF 4352            // 32*136 floats
#define G_BUF  (G_ABUF + G_BBUF)
#define G_SMEM_BYTES (2*G_BUF*4)

// EPI: 1 = exact GELU (rounded store), 2 = res + gate*acc (raw store)
template<int EPI>
__global__ void __launch_bounds__(256, 2) gemm_tc(
    const float* __restrict__ A, const float* __restrict__ W,
    float* __restrict__ Out, int M, int Nc, int K,
    const float* __restrict__ gate, const float* __restrict__ res)
{
    extern __shared__ float sm[];
    const int tid  = threadIdx.x;
    const int lane = tid & 31, warp = tid >> 5;
    const int grp  = lane >> 2, tig = lane & 3;
    const int wm   = warp & 3,  wn  = warp >> 2;
    const int m0   = blockIdx.y * 128, n0 = blockIdx.x * 128;
    const uint32_t smb = smaddr(sm);
    const int nk = K >> 5;

    float acc[2][8][4];
    #pragma unroll
    for (int i = 0; i < 2; i++)
        #pragma unroll
        for (int j = 0; j < 8; j++)
            #pragma unroll
            for (int t = 0; t < 4; t++) acc[i][j][t] = 0.f;

    auto prefetch = [&](int kc, int bufi){
        int off = bufi * G_BUF;
        #pragma unroll
        for (int i = 0; i < 4; i++) {
            int idx = tid + i*256;
            int r = idx >> 3, c4 = (idx & 7) * 4;
            cp16(smb + (uint32_t)(off + r*36 + c4)*4u,
                 A + (size_t)(m0 + r)*K + kc*32 + c4);
        }
        #pragma unroll
        for (int i = 0; i < 4; i++) {
            int idx = tid + i*256;
            int r = idx >> 5, c4 = (idx & 31) * 4;
            cp16(smb + (uint32_t)(off + G_ABUF + r*136 + c4)*4u,
                 W + (size_t)(kc*32 + r)*Nc + n0 + c4);
        }
    };

    prefetch(0, 0); cp_commit();
    int buf = 0;
    for (int kc = 0; kc < nk; kc++) {
        if (kc + 1 < nk) prefetch(kc + 1, buf ^ 1);
        cp_commit();
        cp_wait1();
        __syncthreads();
        const float* As = sm + buf*G_BUF;
        const float* Bs = As + G_ABUF;
        #pragma unroll
        for (int kk = 0; kk < 32; kk += 8) {
            float af[2][4], bf[8][2];
            #pragma unroll
            for (int ma = 0; ma < 2; ma++) {
                int r = wm*32 + ma*16 + grp;
                af[ma][0] = As[r    *36 + kk + tig];
                af[ma][1] = As[(r+8)*36 + kk + tig];
                af[ma][2] = As[r    *36 + kk + tig + 4];
                af[ma][3] = As[(r+8)*36 + kk + tig + 4];
            }
            #pragma unroll
            for (int nb = 0; nb < 8; nb++) {
                int c = wn*64 + nb*8 + grp;
                bf[nb][0] = Bs[(kk+tig  )*136 + c];
                bf[nb][1] = Bs[(kk+tig+4)*136 + c];
            }
            #pragma unroll
            for (int ma = 0; ma < 2; ma++)
                #pragma unroll
                for (int nb = 0; nb < 8; nb++)
                    mma16n8k8(acc[ma][nb], af[ma], bf[nb]);
        }
        __syncthreads();
        buf ^= 1;
    }

    #pragma unroll
    for (int ma = 0; ma < 2; ma++) {
        int r0 = m0 + wm*32 + ma*16 + grp;
        #pragma unroll
        for (int nb = 0; nb < 8; nb++) {
            int c = n0 + wn*64 + nb*8 + 2*tig;
            float o0 = acc[ma][nb][0], o1 = acc[ma][nb][1];
            float o2 = acc[ma][nb][2], o3 = acc[ma][nb][3];
            if (EPI == 1) {
                o0 = to_tf32(0.5f*o0*(1.f + erff(o0*0.70710678f)));
                o1 = to_tf32(0.5f*o1*(1.f + erff(o1*0.70710678f)));
                o2 = to_tf32(0.5f*o2*(1.f + erff(o2*0.70710678f)));
                o3 = to_tf32(0.5f*o3*(1.f + erff(o3*0.70710678f)));
            } else if (EPI == 2) {
                int bi = r0 >> 11;
                float2 g2 = *(const float2*)(gate + bi*6*DIM + c);
                float2 ra = *(const float2*)(res + (size_t)r0    *Nc + c);
                float2 rb = *(const float2*)(res + (size_t)(r0+8)*Nc + c);
                o0 = ra.x + g2.x*o0; o1 = ra.y + g2.y*o1;
                o2 = rb.x + g2.x*o2; o3 = rb.y + g2.y*o3;
            }
            *(float2*)(Out + (size_t)r0    *Nc + c) = make_float2(o0, o1);
            *(float2*)(Out + (size_t)(r0+8)*Nc + c) = make_float2(o2, o3);
        }
    }
}

// Fused QKV: grid.x = 24 (sel = bx>>3 chooses weight/output), tf32-rounded store
__global__ void __launch_bounds__(256, 2) gemm_qkv(
    const float* __restrict__ A,
    const float* __restrict__ Wq, const float* __restrict__ Wk,
    const float* __restrict__ Wv,
    float* __restrict__ oq, float* __restrict__ ok, float* __restrict__ ov)
{
    extern __shared__ float sm[];
    const int tid  = threadIdx.x;
    const int lane = tid & 31, warp = tid >> 5;
    const int grp  = lane >> 2, tig = lane & 3;
    const int wm   = warp & 3,  wn  = warp >> 2;
    const int sel  = blockIdx.x >> 3;
    const int m0   = blockIdx.y * 128, n0 = (blockIdx.x & 7) * 128;
    const float* W = (sel == 0) ? Wq : (sel == 1) ? Wk : Wv;
    float* Out     = (sel == 0) ? oq : (sel == 1) ? ok : ov;
    const uint32_t smb = smaddr(sm);

    float acc[2][8][4];
    #pragma unroll
    for (int i = 0; i < 2; i++)
        #pragma unroll
        for (int j = 0; j < 8; j++)
            #pragma unroll
            for (int t = 0; t < 4; t++) acc[i][j][t] = 0.f;

    auto prefetch = [&](int kc, int bufi){
        int off = bufi * G_BUF;
        #pragma unroll
        for (int i = 0; i < 4; i++) {
            int idx = tid + i*256;
            int r = idx >> 3, c4 = (idx & 7) * 4;
            cp16(smb + (uint32_t)(off + r*36 + c4)*4u,
                 A + (size_t)(m0 + r)*DIM + kc*32 + c4);
        }
        #pragma unroll
        for (int i = 0; i < 4; i++) {
            int idx = tid + i*256;
            int r = idx >> 5, c4 = (idx & 31) * 4;
            cp16(smb + (uint32_t)(off + G_ABUF + r*136 + c4)*4u,
                 W + (size_t)(kc*32 + r)*DIM + n0 + c4);
        }
    };

    prefetch(0, 0); cp_commit();
    int buf = 0;
    for (int kc = 0; kc < DIM/32; kc++) {
        if (kc + 1 < DIM/32) prefetch(kc + 1, buf ^ 1);
        cp_commit();
        cp_wait1();
        __syncthreads();
        const float* As = sm + buf*G_BUF;
        const float* Bs = As + G_ABUF;
        #pragma unroll
        for (int kk = 0; kk < 32; kk += 8) {
            float af[2][4], bf[8][2];
            #pragma unroll
            for (int ma = 0; ma < 2; ma++) {
                int r = wm*32 + ma*16 + grp;
                af[ma][0] = As[r    *36 + kk + tig];
                af[ma][1] = As[(r+8)*36 + kk + tig];
                af[ma][2] = As[r    *36 + kk + tig + 4];
                af[ma][3] = As[(r+8)*36 + kk + tig + 4];
            }
            #pragma unroll
            for (int nb = 0; nb < 8; nb++) {
                int c = wn*64 + nb*8 + grp;
                bf[nb][0] = Bs[(kk+tig  )*136 + c];
                bf[nb][1] = Bs[(kk+tig+4)*136 + c];
            }
            #pragma unroll
            for (int ma = 0; ma < 2; ma++)
                #pragma unroll
                for (int nb = 0; nb < 8; nb++)
                    mma16n8k8(acc[ma][nb], af[ma], bf[nb]);
        }
        __syncthreads();
        buf ^= 1;
    }

    #pragma unroll
    for (int ma = 0; ma < 2; ma++) {
        int r0 = m0 + wm*32 + ma*16 + grp;
        #pragma unroll
        for (int nb = 0; nb < 8; nb++) {
            int c = n0 + wn*64 + nb*8 + 2*tig;
            float o0 = to_tf32(acc[ma][nb][0]);
            float o1 = to_tf32(acc[ma][nb][1]);
            float o2 = to_tf32(acc[ma][nb][2]);
            float o3 = to_tf32(acc[ma][nb][3]);
            *(float2*)(Out + (size_t)r0    *DIM + c) = make_float2(o0, o1);
            *(float2*)(Out + (size_t)(r0+8)*DIM + c) = make_float2(o2, o3);
        }
    }
}

// ---------------------------------------------------------------------------
// 4) RoPE (outputs tf32-rounded — feeds flash MMA)
// ---------------------------------------------------------------------------
__global__ void __launch_bounds__(256) rope_kernel(float* __restrict__ q,
                                                   float* __restrict__ k)
{
    int idx = blockIdx.x*256 + threadIdx.x;
    int n = (idx >> 4) & (NT-1);
    float cs[32], sn[32];
    #pragma unroll
    for (int j = 0; j < 32; j++) {
        float invf = expf((float)j * -0.2878231366f);
        float ang  = (float)n * invf;
        sincosf(ang, &sn[j], &cs[j]);
    }
    float* ptrs[2]; ptrs[0] = q + (size_t)idx*64; ptrs[1] = k + (size_t)idx*64;
    #pragma unroll
    for (int tpi = 0; tpi < 2; tpi++) {
        float* p = ptrs[tpi];
        float buf[64];
        #pragma unroll
        for (int u = 0; u < 16; u++) {
            float4 t = *(const float4*)(p + u*4);
            buf[u*4+0] = t.x; buf[u*4+1] = t.y; buf[u*4+2] = t.z; buf[u*4+3] = t.w;
        }
        #pragma unroll
        for (int t = 0; t < 8; t++) {
            float4 lo, hi;
            lo.x = to_tf32(buf[4*t+0]*cs[4*t+0] - buf[8*t+1]*sn[4*t+0]);
            lo.y = to_tf32(buf[4*t+1]*cs[4*t+1] - buf[8*t+3]*sn[4*t+1]);
            lo.z = to_tf32(buf[4*t+2]*cs[4*t+2] - buf[8*t+5]*sn[4*t+2]);
            lo.w = to_tf32(buf[4*t+3]*cs[4*t+3] - buf[8*t+7]*sn[4*t+3]);
            hi.x = to_tf32(buf[32+4*t+0]*cs[4*t+0] + buf[8*t+0]*sn[4*t+0]);
            hi.y = to_tf32(buf[32+4*t+1]*cs[4*t+1] + buf[8*t+2]*sn[4*t+1]);
            hi.z = to_tf32(buf[32+4*t+2]*cs[4*t+2] + buf[8*t+4]*sn[4*t+2]);
            hi.w = to_tf32(buf[32+4*t+3]*cs[4*t+3] + buf[8*t+6]*sn[4*t+3]);
            *(float4*)(p + 4*t)      = lo;
            *(float4*)(p + 32 + 4*t) = hi;
        }
    }
}

// ---------------------------------------------------------------------------
// 5) Flash attention (tf32 mma; inputs pre-rounded, so no cvt on tile fill)
// ---------------------------------------------------------------------------
#define F_QS 0
#define F_KS 4352
#define F_VS 8704
#define F_PS 13312
#define F_SMEM_BYTES (17664*4)

__global__ void __launch_bounds__(128) flash_tc(
    const float* __restrict__ q, const float* __restrict__ k,
    const float* __restrict__ v, float* __restrict__ o)
{
    extern __shared__ float sm[];
    float* Qs = sm + F_QS;
    float* Ks = sm + F_KS;
    float* Vs = sm + F_VS;
    float* Ps = sm + F_PS;

    const int qt = blockIdx.x, bh = blockIdx.y;
    const int b = bh >> 4, h = bh & 15;
    const int tid = threadIdx.x;
    const int lane = tid & 31, warp = tid >> 5;
    const int grp = lane >> 2, tig = lane & 3;
    const int wrow = warp * 16;
    const float* qb = q + (size_t)b*NT*DIM + h*HD;
    const float* kb = k + (size_t)b*NT*DIM + h*HD;
    const float* vb = v + (size_t)b*NT*DIM + h*HD;

    // q pre-rounded; *0.125f is an exact exponent shift (stays tf32)
    #pragma unroll
    for (int i = 0; i < 8; i++) {
        int idx = tid + i*128;
        int r = idx >> 4, c4 = (idx & 15) * 4;
        float4 t = *(const float4*)(qb + (size_t)(qt*64 + r)*DIM + c4);
        t.x *= 0.125f; t.y *= 0.125f; t.z *= 0.125f; t.w *= 0.125f;
        *(float4*)(Qs + r*68 + c4) = t;
    }

    float O[8][4];
    #pragma unroll
    for (int i = 0; i < 8; i++)
        #pragma unroll
        for (int j = 0; j < 4; j++) O[i][j] = 0.f;
    float m0 = -1e30f, m1 = -1e30f, l0 = 0.f, l1 = 0.f;

    for (int kt = 0; kt < NT/64; kt++) {
        __syncthreads();
        #pragma unroll
        for (int i = 0; i < 8; i++) {
            int idx = tid + i*128;
            int r = idx >> 4, c4 = (idx & 15) * 4;
            float4 kv = *(const float4*)(kb + (size_t)(kt*64 + r)*DIM + c4);
            *(float4*)(Ks + r*68 + c4) = kv;
            float4 vv = *(const float4*)(vb + (size_t)(kt*64 + r)*DIM + c4);
            *(float4*)(Vs + r*72 + c4) = vv;
        }
        __syncthreads();

        float s[8][4];
        #pragma unroll
        for (int i = 0; i < 8; i++)
            #pragma unroll
            for (int j = 0; j < 4; j++) s[i][j] = 0.f;
        #pragma unroll
        for (int kk = 0; kk < 64; kk += 8) {
            float af[4];
            af[0] = Qs[(wrow+grp  )*68 + kk + tig];
            af[1] = Qs[(wrow+grp+8)*68 + kk + tig];
            af[2] = Qs[(wrow+grp  )*68 + kk + tig + 4];
            af[3] = Qs[(wrow+grp+8)*68 + kk + tig + 4];
            #pragma unroll
            for (int nb = 0; nb < 8; nb++) {
                float bf[2];
                bf[0] = Ks[(nb*8+grp)*68 + kk + tig];
                bf[1] = Ks[(nb*8+grp)*68 + kk + tig + 4];
                mma16n8k8(s[nb], af, bf);
            }
        }

        float mx0 = -1e30f, mx1 = -1e30f;
        #pragma unroll
        for (int nb = 0; nb < 8; nb++) {
            mx0 = fmaxf(mx0, fmaxf(s[nb][0], s[nb][1]));
            mx1 = fmaxf(mx1, fmaxf(s[nb][2], s[nb][3]));
        }
        mx0 = fmaxf(mx0, __shfl_xor_sync(0xffffffffu, mx0, 1));
        mx0 = fmaxf(mx0, __shfl_xor_sync(0xffffffffu, mx0, 2));
        mx1 = fmaxf(mx1, __shfl_xor_sync(0xffffffffu, mx1, 1));
        mx1 = fmaxf(mx1, __shfl_xor_sync(0xffffffffu, mx1, 2));
        float nm0 = fmaxf(m0, mx0), nm1 = fmaxf(m1, mx1);
        float a0 = __expf(m0 - nm0), a1 = __expf(m1 - nm1);
        float rs0 = 0.f, rs1 = 0.f;
        #pragma unroll
        for (int nb = 0; nb < 8; nb++) {
            float p0 = to_tf32(__expf(s[nb][0] - nm0));
            float p1 = to_tf32(__expf(s[nb][1] - nm0));
            float p2 = to_tf32(__expf(s[nb][2] - nm1));
            float p3 = to_tf32(__expf(s[nb][3] - nm1));
            rs0 += p0 + p1; rs1 += p2 + p3;
            *(float2*)(Ps + (wrow+grp  )*68 + nb*8 + 2*tig) = make_float2(p0, p1);
            *(float2*)(Ps + (wrow+grp+8)*68 + nb*8 + 2*tig) = make_float2(p2, p3);
            O[nb][0] *= a0; O[nb][1] *= a0;
            O[nb][2] *= a1; O[nb][3] *= a1;
        }
        rs0 += __shfl_xor_sync(0xffffffffu, rs0, 1);
        rs0 += __shfl_xor_sync(0xffffffffu, rs0, 2);
        rs1 += __shfl_xor_sync(0xffffffffu, rs1, 1);
        rs1 += __shfl_xor_sync(0xffffffffu, rs1, 2);
        l0 = l0*a0 + rs0; l1 = l1*a1 + rs1;
        m0 = nm0; m1 = nm1;
        __syncwarp();

        #pragma unroll
        for (int kk = 0; kk < 64; kk += 8) {
            float af[4];
            af[0] = Ps[(wrow+grp  )*68 + kk + tig];
            af[1] = Ps[(wrow+grp+8)*68 + kk + tig];
            af[2] = Ps[(wrow+grp  )*68 + kk + tig + 4];
            af[3] = Ps[(wrow+grp+8)*68 + kk + tig + 4];
            #pragma unroll
            for (int nb = 0; nb < 8; nb++) {
                float bf[2];
                bf[0] = Vs[(kk+tig  )*72 + nb*8 + grp];
                bf[1] = Vs[(kk+tig+4)*72 + nb*8 + grp];
                mma16n8k8(O[nb], af, bf);
            }
        }
        __syncwarp();
    }

    float i0 = 1.f/l0, i1 = 1.f/l1;
    int row = qt*64 + wrow + grp;
    #pragma unroll
    for (int nb = 0; nb < 8; nb++) {
        float* op = o + (size_t)(b*NT + row)*DIM + h*HD + nb*8 + 2*tig;
        *(float2*)op           = make_float2(to_tf32(O[nb][0]*i0), to_tf32(O[nb][1]*i0));
        *(float2*)(op + 8*DIM) = make_float2(to_tf32(O[nb][2]*i1), to_tf32(O[nb][3]*i1));
    }
}

// ---------------------------------------------------------------------------
// Host launcher
// ---------------------------------------------------------------------------
extern "C" void kernel_launch(void* const* d_in, const int* in_sizes, int n_in,
                              void* d_out, int out_size)
{
    const float* x       = (const float*)d_in[0];
    const float* t_emb   = (const float*)d_in[1];
    const float* norm1_g = (const float*)d_in[2];
    const float* norm1_b = (const float*)d_in[3];
    const float* Wq      = (const float*)d_in[4];
    const float* Wk      = (const float*)d_in[5];
    const float* Wv      = (const float*)d_in[6];
    const float* Wo      = (const float*)d_in[7];
    const float* norm2_g = (const float*)d_in[8];
    const float* norm2_b = (const float*)d_in[9];
    const float* W1      = (const float*)d_in[10];
    const float* W2      = (const float*)d_in[11];
    const float* ada_W   = (const float*)d_in[12];
    const float* ada_b   = (const float*)d_in[13];
    float* out = (float*)d_out;

    float *mod, *xn, *q, *k, *v, *attn, *hbuf, *wt;
    cudaGetSymbolAddress((void**)&mod,  g_mod);
    cudaGetSymbolAddress((void**)&xn,   g_xn);
    cudaGetSymbolAddress((void**)&q,    g_q);
    cudaGetSymbolAddress((void**)&k,    g_k);
    cudaGetSymbolAddress((void**)&v,    g_v);
    cudaGetSymbolAddress((void**)&attn, g_attn);
    cudaGetSymbolAddress((void**)&hbuf, g_h);
    cudaGetSymbolAddress((void**)&wt,   g_wt);

    float* wq = wt;
    float* wk = wt + 1024*1024;
    float* wv = wt + 2*1024*1024;
    float* wo = wt + 3*1024*1024;
    float* w1 = wt + 4*1024*1024;
    float* w2 = wt + 8*1024*1024;

    cudaFuncSetAttribute(gemm_qkv,
        cudaFuncAttributeMaxDynamicSharedMemorySize, G_SMEM_BYTES);
    cudaFuncSetAttribute(gemm_tc<1>,
        cudaFuncAttributeMaxDynamicSharedMemorySize, G_SMEM_BYTES);
    cudaFuncSetAttribute(gemm_tc<2>,
        cudaFuncAttributeMaxDynamicSharedMemorySize, G_SMEM_BYTES);
    cudaFuncSetAttribute(flash_tc,
        cudaFuncAttributeMaxDynamicSharedMemorySize, F_SMEM_BYTES);

    // 0. Pre-round weights to tf32 (once per launch, fully overlappable)
    round_tf32_kernel<<<1024, 256>>>(Wq, wq, 262144);
    round_tf32_kernel<<<1024, 256>>>(Wk, wk, 262144);
    round_tf32_kernel<<<1024, 256>>>(Wv, wv, 262144);
    round_tf32_kernel<<<1024, 256>>>(Wo, wo, 262144);
    round_tf32_kernel<<<4096, 256>>>(W1, w1, 1048576);
    round_tf32_kernel<<<4096, 256>>>(W2, w2, 1048576);

    // 1. adaLN modulation
    silu_mod_kernel<<<dim3(24, BT), 256>>>(t_emb, ada_W, ada_b, mod);
    // 2. LN1 + modulate (shift=0, scale=1) — tf32-rounded output
    ln_mod_kernel<<<ROWS, 256>>>(x, xn, norm1_g, norm1_b, mod, 0, 1);
    // 3. Fused QKV projections
    gemm_qkv<<<dim3(24, ROWS/128), 256, G_SMEM_BYTES>>>(xn, wq, wk, wv, q, k, v);
    // 4. RoPE (tf32-rounded output)
    rope_kernel<<<(BT*NT*HEADS)/256, 256>>>(q, k);
    // 5. attention
    flash_tc<<<dim3(NT/64, BT*HEADS), 128, F_SMEM_BYTES>>>(q, k, v, attn);
    // 6. out proj + gated residual (gate_msa = chunk 2) -> d_out
    gemm_tc<2><<<dim3(8, ROWS/128), 256, G_SMEM_BYTES>>>(
        attn, wo, out, ROWS, DIM, DIM, mod + 2*DIM, x);
    // 7. LN2 + modulate (shift=3, scale=4)
    ln_mod_kernel<<<ROWS, 256>>>(out, xn, norm2_g, norm2_b, mod, 3, 4);
    // 8. MLP up + exact GELU (tf32-rounded output)
    gemm_tc<1><<<dim3(32, ROWS/128), 256, G_SMEM_BYTES>>>(
        xn, w1, hbuf, ROWS, MLPD, DIM, nullptr, nullptr);
    // 9. MLP down + gated residual (gate_mlp = chunk 5) -> d_out
    gemm_tc<2><<<dim3(8, ROWS/128), 256, G_SMEM_BYTES>>>(
        hbuf, w2, out, ROWS, DIM, MLPD, mod + 5*DIM, out);
}